// round 9
// baseline (speedup 1.0000x reference)
#include <cuda_runtime.h>
#include <cuda_bf16.h>

#define Bb   16
#define Nn   8
#define Tt   65536
#define CPB  32            // chunks per batch
#define TPB  128
#define NVALS 80           // 64 gram + 8 sum(x^2) + 8 sum(y^2)
#define ITERS ((Tt / CPB) / 4 / TPB)   // = 4 float4 iterations per thread
#define GRID (Bb * CPB)

// Deterministic scratch for per-chunk partial sums (no atomics anywhere).
__device__ float g_partial[GRID * NVALS];

__device__ __forceinline__ float dot4(float4 a, float4 b) {
    return a.x * b.x + a.y * b.y + a.z * b.z + a.w * b.w;
}

// ---------------------------------------------------------------------------
// Kernel 1: EXACT R2 gram (best measured config, 21.2us total).
// This round launches it TWICE back-to-back (idempotent — second run writes
// bit-identical partials) so dur(R9) - dur(R2) = in-run T_gram + launch gap.
// That differential finally splits the 21.2us between gram / sink / overhead.
// ---------------------------------------------------------------------------
__global__ __launch_bounds__(TPB) void k_gram(const float* __restrict__ inp,
                                              const float* __restrict__ tgt) {
    const int b   = blockIdx.x / CPB;
    const int c   = blockIdx.x % CPB;
    const int tid = threadIdx.x;

    const float4* ip = reinterpret_cast<const float4*>(inp) + (size_t)b * Nn * (Tt / 4);
    const float4* tp = reinterpret_cast<const float4*>(tgt) + (size_t)b * Nn * (Tt / 4);
    const int base = c * (Tt / CPB / 4) + tid;

    float acc[NVALS];
#pragma unroll
    for (int v = 0; v < NVALS; v++) acc[v] = 0.f;

#pragma unroll
    for (int k = 0; k < ITERS; k++) {
        const int idx = base + k * TPB;
        float4 av[Nn], bv[Nn];
#pragma unroll
        for (int i = 0; i < Nn; i++) av[i] = ip[i * (Tt / 4) + idx];
#pragma unroll
        for (int j = 0; j < Nn; j++) bv[j] = tp[j * (Tt / 4) + idx];
#pragma unroll
        for (int i = 0; i < Nn; i++) acc[64 + i] += dot4(av[i], av[i]);
#pragma unroll
        for (int j = 0; j < Nn; j++) acc[72 + j] += dot4(bv[j], bv[j]);
#pragma unroll
        for (int i = 0; i < Nn; i++)
#pragma unroll
            for (int j = 0; j < Nn; j++)
                acc[i * 8 + j] += dot4(av[i], bv[j]);
    }

    // Fixed-order reduction: warp shuffle then cross-warp via smem.
    __shared__ float sm[TPB / 32][NVALS];
    const int lane = tid & 31, warp = tid >> 5;
#pragma unroll
    for (int v = 0; v < NVALS; v++) {
        float x = acc[v];
#pragma unroll
        for (int off = 16; off; off >>= 1) x += __shfl_down_sync(0xffffffffu, x, off);
        if (lane == 0) sm[warp][v] = x;
    }
    __syncthreads();
    if (tid < NVALS) {
        float s = 0.f;
#pragma unroll
        for (int w = 0; w < TPB / 32; w++) s += sm[w][tid];
        g_partial[blockIdx.x * NVALS + tid] = s;
    }
}

// ---------------------------------------------------------------------------
// Kernel 2: EXACT R2 sink. 512 threads. Phase A: parallel chunk reduction.
// Phase B: one warp per batch, linear-domain all-shuffle Sinkhorn.
// ---------------------------------------------------------------------------
__global__ __launch_bounds__(512) void k_sink(float* __restrict__ out, int out_size) {
    __shared__ float G[Bb][NVALS];
    __shared__ float bloss[Bb];

    const int tid = threadIdx.x;

    for (int v = tid; v < Bb * NVALS; v += 512) {
        const int b = v / NVALS, k = v % NVALS;
        const float* p = &g_partial[b * CPB * NVALS + k];
        float s = 0.f;
#pragma unroll
        for (int c = 0; c < CPB; c++) s += p[c * NVALS];
        G[b][k] = s;
    }
    __syncthreads();

    const int w  = tid >> 5;
    const int l  = tid & 31;
    const int j  = l & 7;
    const int i0 = l >> 3;
    const int i1 = i0 + 4;
    const float invT = 1.0f / (float)Tt;

    if (w < Bb) {
        const float L0 = (G[w][64 + i0] + G[w][72 + j] - 2.f * G[w][i0 * 8 + j]) * invT;
        const float L1 = (G[w][64 + i1] + G[w][72 + j] - 2.f * G[w][i1 * 8 + j]) * invT;
        float p0 = __expf(-L0), p1 = __expf(-L1);   // P = exp(-COLDNESS*L)

#pragma unroll
        for (int it = 0; it < 10; it++) {
            float s = p0 + p1;
            s += __shfl_xor_sync(0xffffffffu, s, 8);
            s += __shfl_xor_sync(0xffffffffu, s, 16);
            const float r = __fdividef(1.f, s);
            p0 *= r;
            p1 *= r;

            float s0 = p0, s1 = p1;
            s0 += __shfl_xor_sync(0xffffffffu, s0, 1);
            s1 += __shfl_xor_sync(0xffffffffu, s1, 1);
            s0 += __shfl_xor_sync(0xffffffffu, s0, 2);
            s1 += __shfl_xor_sync(0xffffffffu, s1, 2);
            s0 += __shfl_xor_sync(0xffffffffu, s0, 4);
            s1 += __shfl_xor_sync(0xffffffffu, s1, 4);
            p0 *= __fdividef(1.f, s0);
            p1 *= __fdividef(1.f, s1);
        }

        float lp = (L0 + __logf(p0)) * p0 + (L1 + __logf(p1)) * p1;
#pragma unroll
        for (int off = 16; off; off >>= 1) lp += __shfl_xor_sync(0xffffffffu, lp, off);
        if (l == 0) bloss[w] = lp;

        float v0 = p0, v1 = p1;
        int   a0 = j,  a1 = j;
#pragma unroll
        for (int off = 1; off <= 4; off <<= 1) {
            float ov = __shfl_xor_sync(0xffffffffu, v0, off);
            int   oa = __shfl_xor_sync(0xffffffffu, a0, off);
            if (ov > v0 || (ov == v0 && oa < a0)) { v0 = ov; a0 = oa; }
            ov = __shfl_xor_sync(0xffffffffu, v1, off);
            oa = __shfl_xor_sync(0xffffffffu, a1, off);
            if (ov > v1 || (ov == v1 && oa < a1)) { v1 = ov; a1 = oa; }
        }
        if (out_size >= 1 + Bb * Nn && j == 0) {
            out[1 + w * Nn + i0] = (float)a0;
            out[1 + w * Nn + i1] = (float)a1;
        }
    }

    __syncthreads();
    if (tid == 0) {
        float s = 0.f;
#pragma unroll
        for (int b = 0; b < Bb; b++) s += bloss[b];
        out[0] = s * (1.0f / (float)Bb);
    }
}

// ---------------------------------------------------------------------------
extern "C" void kernel_launch(void* const* d_in, const int* in_sizes, int n_in,
                              void* d_out, int out_size) {
    const float* inp = (const float*)d_in[0];
    const float* tgt = (const float*)d_in[1];
    // Differential timing round: gram launched twice (idempotent).
    // dur(R9) - 21.2us isolates in-run T_gram + one launch gap.
    k_gram<<<GRID, TPB>>>(inp, tgt);
    k_gram<<<GRID, TPB>>>(inp, tgt);
    k_sink<<<1, 512>>>((float*)d_out, out_size);
}

// round 10
// speedup vs baseline: 1.3556x; 1.3556x over previous
#include <cuda_runtime.h>
#include <cuda_bf16.h>

#define Bb   16
#define Nn   8
#define Tt   65536
#define CPB  32            // chunks per batch
#define TPB  128
#define NVALS 80           // 64 gram + 8 sum(x^2) + 8 sum(y^2)
#define ITERS ((Tt / CPB) / 4 / TPB)   // = 4 (16B per thread-iter per row)
#define GRID (Bb * CPB)    // 512 blocks

// Partials laid out [batch][value][chunk] -> tail reduces contiguous 128B runs.
// No float atomics anywhere -> deterministic.
__device__ float g_partial[Bb * NVALS * CPB];
__device__ unsigned int g_count = 0;

typedef unsigned long long u64;

// d(lo,hi) += a(lo,hi) * b(lo,hi)  — packed fp32x2 FFMA (PTX-only on sm_103a).
__device__ __forceinline__ void ffma2(u64& d, u64 a, u64 b) {
    asm("fma.rn.f32x2 %0, %1, %2, %0;" : "+l"(d) : "l"(a), "l"(b));
}
__device__ __forceinline__ float unpack_sum(u64 v) {
    float lo, hi;
    asm("mov.b64 {%0, %1}, %2;" : "=f"(lo), "=f"(hi) : "l"(v));
    return lo + hi;
}

// ---------------------------------------------------------------------------
// Fused kernel, launch_bounds(128,2) -> 255-reg budget (standalone gram
// measured 178 regs no-spill; R3's fusion failed because ptxas's default
// squeezed to 142 and spilled — fixed here by the explicit budget).
//
// Gram loop: t-packed FFMA2. Each 16B row-load is a ulonglong2 whose halves
// are natural (f32,f32) pairs — zero packing MOVs. Each u64 accumulator keeps
// (sum over even t, sum over odd t); one lo+hi add at the end. FFMA-pipe
// issue per iter: 160 FFMA2 vs 320 FFMA — halving the ~5us chip issue floor.
//
// Tail (last finishing block): contiguous Phase-A reduction + thread-per-
// (batch,row) linear-domain Sinkhorn (R3-proven), loss + argmax.
// ---------------------------------------------------------------------------
__global__ __launch_bounds__(TPB, 2) void k_fused(const float* __restrict__ inp,
                                                  const float* __restrict__ tgt,
                                                  float* __restrict__ out,
                                                  int out_size) {
    const int b   = blockIdx.x / CPB;
    const int c   = blockIdx.x % CPB;
    const int tid = threadIdx.x;

    // ---------------- Gram partials (FFMA2, t-packed) ----------------
    {
        const ulonglong2* ip = reinterpret_cast<const ulonglong2*>(inp)
                             + (size_t)b * Nn * (Tt / 4);
        const ulonglong2* tp = reinterpret_cast<const ulonglong2*>(tgt)
                             + (size_t)b * Nn * (Tt / 4);
        const int base = c * (Tt / CPB / 4) + tid;

        u64 cr[Nn][Nn];      // cross: (even-t sum, odd-t sum)
        u64 sx[Nn], sy[Nn];
#pragma unroll
        for (int i = 0; i < Nn; i++) {
            sx[i] = 0ull; sy[i] = 0ull;
#pragma unroll
            for (int j = 0; j < Nn; j++) cr[i][j] = 0ull;
        }

#pragma unroll
        for (int k = 0; k < ITERS; k++) {
            const int idx = base + k * TPB;
            ulonglong2 av[Nn], bv[Nn];
#pragma unroll
            for (int i = 0; i < Nn; i++) av[i] = ip[i * (Tt / 4) + idx];
#pragma unroll
            for (int j = 0; j < Nn; j++) bv[j] = tp[j * (Tt / 4) + idx];

#pragma unroll
            for (int i = 0; i < Nn; i++) {
                ffma2(sx[i], av[i].x, av[i].x);
                ffma2(sx[i], av[i].y, av[i].y);
                ffma2(sy[i], bv[i].x, bv[i].x);
                ffma2(sy[i], bv[i].y, bv[i].y);
            }
#pragma unroll
            for (int i = 0; i < Nn; i++)
#pragma unroll
                for (int j = 0; j < Nn; j++) {
                    ffma2(cr[i][j], av[i].x, bv[j].x);
                    ffma2(cr[i][j], av[i].y, bv[j].y);
                }
        }

        float acc[NVALS];
#pragma unroll
        for (int i = 0; i < Nn; i++) {
#pragma unroll
            for (int j = 0; j < Nn; j++) acc[i * 8 + j] = unpack_sum(cr[i][j]);
            acc[64 + i] = unpack_sum(sx[i]);
            acc[72 + i] = unpack_sum(sy[i]);
        }

        // Fixed-order reduction: warp shuffle then cross-warp via smem.
        __shared__ float sm[TPB / 32][NVALS];
        const int lane = tid & 31, warp = tid >> 5;
#pragma unroll
        for (int v = 0; v < NVALS; v++) {
            float x = acc[v];
#pragma unroll
            for (int off = 16; off; off >>= 1) x += __shfl_down_sync(0xffffffffu, x, off);
            if (lane == 0) sm[warp][v] = x;
        }
        __syncthreads();
        if (tid < NVALS) {
            float s = 0.f;
#pragma unroll
            for (int w = 0; w < TPB / 32; w++) s += sm[w][tid];
            g_partial[(b * NVALS + tid) * CPB + c] = s;   // [b][val][chunk]
        }
    }

    // ---------------- Last-block election ----------------
    __shared__ int is_last;
    __syncthreads();
    if (tid == 0) {
        __threadfence();                                  // publish partials
        unsigned int prev = atomicAdd(&g_count, 1u);
        is_last = (prev == GRID - 1);
        if (is_last) g_count = 0;                         // reset for replay
    }
    __syncthreads();
    if (!is_last) return;
    __threadfence();                                      // acquire partials

    // ---------------- Tail: reduce + Sinkhorn ----------------
    __shared__ float G[Bb][NVALS];
    __shared__ float lsum[TPB];

    for (int v = tid; v < Bb * NVALS; v += TPB) {
        const float4* p = reinterpret_cast<const float4*>(&g_partial[v * CPB]);
        float s = 0.f;
#pragma unroll
        for (int q = 0; q < CPB / 4; q++) {
            const float4 x = p[q];
            s += x.x + x.y + x.z + x.w;
        }
        G[v / NVALS][v % NVALS] = s;
    }
    __syncthreads();

    const int bb = tid >> 3;            // batch (16)
    const int i  = tid & 7;             // row   (8)
    const float invT = 1.0f / (float)Tt;

    float L[Nn], P[Nn];
    const float sxi = G[bb][64 + i];
#pragma unroll
    for (int j = 0; j < Nn; j++) {
        L[j] = (sxi + G[bb][72 + j] - 2.f * G[bb][i * 8 + j]) * invT;
        P[j] = __expf(-L[j]);           // P = exp(-COLDNESS*L)
    }

    // Linear-domain Sinkhorn: col-normalize (shfl over the 8 rows of this
    // batch, which are 8 consecutive lanes) then row-normalize (in-thread).
#pragma unroll
    for (int it = 0; it < 10; it++) {
        float cs[Nn];
#pragma unroll
        for (int j = 0; j < Nn; j++) cs[j] = P[j];
#pragma unroll
        for (int off = 1; off <= 4; off <<= 1)
#pragma unroll
            for (int j = 0; j < Nn; j++)
                cs[j] += __shfl_xor_sync(0xffffffffu, cs[j], off);
#pragma unroll
        for (int j = 0; j < Nn; j++) P[j] *= __fdividef(1.f, cs[j]);

        float rs = 0.f;
#pragma unroll
        for (int j = 0; j < Nn; j++) rs += P[j];
        const float rr = __fdividef(1.f, rs);
#pragma unroll
        for (int j = 0; j < Nn; j++) P[j] *= rr;
    }

    // Loss: sum_j (L + ln P) * P per row; argmax_j P (first occurrence).
    float lp = 0.f;
    int best = 0;
    float bv = P[0];
#pragma unroll
    for (int j = 0; j < Nn; j++) {
        lp += (L[j] + __logf(P[j])) * P[j];
        if (P[j] > bv) { bv = P[j]; best = j; }
    }
    lsum[tid] = lp;
    if (out_size >= 1 + Bb * Nn) out[1 + tid] = (float)best;
    __syncthreads();

    if (tid == 0) {
        float s = 0.f;
#pragma unroll
        for (int k = 0; k < TPB; k++) s += lsum[k];
        out[0] = s * (1.0f / (float)Bb);
    }
}

// ---------------------------------------------------------------------------
extern "C" void kernel_launch(void* const* d_in, const int* in_sizes, int n_in,
                              void* d_out, int out_size) {
    const float* inp = (const float*)d_in[0];
    const float* tgt = (const float*)d_in[1];
    k_fused<<<GRID, TPB>>>(inp, tgt, (float*)d_out, out_size);
}